// round 4
// baseline (speedup 1.0000x reference)
#include <cuda_runtime.h>
#include <math.h>

#define BB   4
#define NN   10000
#define EE   100000
#define CIN  16
#define NF   128
#define WN   384
#define OUTD 40
#define MROWS (BB*EE)            // 400000
#define ALPHA_C 0.25f
#define BN_EPS_C 1e-5f
#define M_TOT 40000.0f           // B*N rows in BN stats (4*10000)

// ---------------- scratch (device globals; no allocations allowed) ----------
__device__ float g_xnew[BB*NN*CIN];        // time-mixed x, 2.56 MB
__device__ float g_h[MROWS*NF];            // hidden MLP activations, 204.8 MB
__device__ float g_agg[BB*NN*OUTD];        // segment sums -> agg
__device__ float g_cnt[NN];
__device__ float g_sum[OUTD];
__device__ float g_sumsq[OUTD];

// ---------------- zero scratch ----------------------------------------------
__global__ void zero_kernel() {
    int i = blockIdx.x * blockDim.x + threadIdx.x;
    if (i < BB*NN*OUTD) g_agg[i] = 0.0f;
    if (i < NN)         g_cnt[i] = 0.0f;
    if (i < OUTD) { g_sum[i] = 0.0f; g_sumsq[i] = 0.0f; }
}

// ---------------- closed-form FFT time mixing -------------------------------
// x_new[0] = 0.25*(X0r + 2ReX1); [1] = 0.25*(X0r - 2ImX1);
// [2] = 0.25*(X0r - 2ReX1);      [3] = 0.25*(X0r + 2ImX1)
__global__ void xnew_kernel(const float* __restrict__ x,
                            const float* __restrict__ wr,
                            const float* __restrict__ wi) {
    __shared__ float sWr[CIN][CIN];
    __shared__ float sWi[CIN][CIN];
    int t = threadIdx.x;
    {   // sum over MODES=2: tc_w* shape (16,16,2)
        int i = t >> 4, o = t & 15;
        sWr[i][o] = wr[i*32 + o*2 + 0] + wr[i*32 + o*2 + 1];
        sWi[i][o] = wi[i*32 + o*2 + 0] + wi[i*32 + o*2 + 1];
    }
    __syncthreads();
    int idx = blockIdx.x * blockDim.x + t;
    if (idx >= NN*CIN) return;
    int n = idx >> 4, o = idx & 15;
    float x0r = 0.f, re1 = 0.f, im1 = 0.f;
    #pragma unroll
    for (int i = 0; i < CIN; i++) {
        float a0 = x[(0*NN + n)*CIN + i];
        float a1 = x[(1*NN + n)*CIN + i];
        float a2 = x[(2*NN + n)*CIN + i];
        float a3 = x[(3*NN + n)*CIN + i];
        float S = a0 + a1 + a2 + a3;
        float P = a0 - a2;
        float Q = a3 - a1;
        float wrv = sWr[i][o], wiv = sWi[i][o];
        x0r += S * wrv;
        re1 += P * wrv - Q * wiv;
        im1 += P * wiv + Q * wrv;
    }
    g_xnew[(0*NN + n)*CIN + o] = 0.25f*(x0r + 2.f*re1);
    g_xnew[(1*NN + n)*CIN + o] = 0.25f*(x0r - 2.f*im1);
    g_xnew[(2*NN + n)*CIN + o] = 0.25f*(x0r - 2.f*re1);
    g_xnew[(3*NN + n)*CIN + o] = 0.25f*(x0r + 2.f*im1);
}

// ---------------- per-node in-degree ----------------------------------------
__global__ void count_kernel(const int* __restrict__ eidx) {
    int e = blockIdx.x * blockDim.x + threadIdx.x;
    if (e < EE) atomicAdd(&g_cnt[eidx[EE + e]], 1.0f);
}

// ---------------- GEMM1: H = relu(EA @ W1 + b1) -----------------------------
// M=400000, K=128, N=128. Block: 64 rows x 128 cols, 256 threads, TM=4, TN=8.
__global__ __launch_bounds__(256)
void gemm1_kernel(const float* __restrict__ A, const float* __restrict__ W1,
                  const float* __restrict__ b1) {
    __shared__ float As[16][65];     // k-major, padded
    __shared__ float Ws[16*128];
    int tid = threadIdx.x;
    int tx = tid & 15, ty = tid >> 4;      // tx: col group, ty: row group
    int row0 = blockIdx.x * 64;
    float acc[4][8];
    #pragma unroll
    for (int m = 0; m < 4; m++)
        #pragma unroll
        for (int n = 0; n < 8; n++) acc[m][n] = 0.f;

    for (int k0 = 0; k0 < NF; k0 += 16) {
        // load A tile 64x16 (transpose into k-major)
        {
            int r  = tid >> 2;
            int kq = (tid & 3) * 4;
            float4 av = *(const float4*)&A[(row0 + r)*NF + k0 + kq];
            As[kq+0][r] = av.x; As[kq+1][r] = av.y;
            As[kq+2][r] = av.z; As[kq+3][r] = av.w;
        }
        // load W1 tile 16x128
        {
            int kr = tid >> 4;
            int c  = (tid & 15) * 8;
            float4 w0 = *(const float4*)&W1[(k0+kr)*NF + c];
            float4 w1v = *(const float4*)&W1[(k0+kr)*NF + c + 4];
            *(float4*)&Ws[kr*128 + c]     = w0;
            *(float4*)&Ws[kr*128 + c + 4] = w1v;
        }
        __syncthreads();
        #pragma unroll
        for (int kk = 0; kk < 16; kk++) {
            float hf[4], wf[8];
            #pragma unroll
            for (int m = 0; m < 4; m++) hf[m] = As[kk][ty*4 + m];
            #pragma unroll
            for (int n = 0; n < 8; n++) wf[n] = Ws[kk*128 + n*16 + tx];
            #pragma unroll
            for (int m = 0; m < 4; m++)
                #pragma unroll
                for (int n = 0; n < 8; n++) acc[m][n] += hf[m]*wf[n];
        }
        __syncthreads();
    }
    // epilogue: relu + bias
    float bias[8];
    #pragma unroll
    for (int n = 0; n < 8; n++) bias[n] = b1[n*16 + tx];
    #pragma unroll
    for (int m = 0; m < 4; m++) {
        int row = row0 + ty*4 + m;
        #pragma unroll
        for (int n = 0; n < 8; n++) {
            float v = acc[m][n] + bias[n];
            g_h[row*NF + n*16 + tx] = v > 0.f ? v : 0.f;
        }
    }
}

// ---------------- GEMM2 + message + scatter ---------------------------------
// ew = H @ W2 + b2 (per 32-row tile), then per edge-row:
//   out0[o]   = 0.25*sh0*sum_i xg[i]*ew[i*16+o]          (16 ch)
//   out1[o,m] = 0.25*sh1[m]*sum_i xg[i]*ew[256+i*8+o]    (8x3 ch, c=16+o*3+m)
// atomicAdd into g_agg[b, dst, :].
__global__ __launch_bounds__(256)
void gemm2_msg_kernel(const float* __restrict__ W2, const float* __restrict__ b2,
                      const int* __restrict__ eidx, const float* __restrict__ esh) {
    __shared__ float smem[12288];      // 48 KB: Hs(16x33)+Ws2(16x384) | sEw(32x384)
    float* Hs  = smem;                 // 528 floats
    float* Ws2 = smem + 544;           // 6144 floats (16B aligned)
    int tid = threadIdx.x;
    int tx = tid & 31, ty = tid >> 5;  // tx: col lane, ty: row group (0..7)
    int row0 = blockIdx.x * 32;

    float acc[4][12];
    #pragma unroll
    for (int n = 0; n < 12; n++) {
        float bias = b2[n*32 + tx];
        #pragma unroll
        for (int m = 0; m < 4; m++) acc[m][n] = bias;
    }

    for (int k0 = 0; k0 < NF; k0 += 16) {
        // load H tile 32 rows x 16 k (k-major, padded stride 33)
        #pragma unroll
        for (int t = 0; t < 2; t++) {
            int lin = tid + t*256;           // 0..511
            int r = lin >> 4, kk = lin & 15;
            Hs[kk*33 + r] = g_h[(row0 + r)*NF + k0 + kk];
        }
        // load W2 chunk 16 x 384
        #pragma unroll
        for (int t = 0; t < 6; t++) {
            int lin = tid + t*256;           // 0..1535 float4s
            int k = lin / 96, c4 = lin % 96;
            float4 w = *(const float4*)&W2[(k0 + k)*WN + c4*4];
            *(float4*)&Ws2[k*WN + c4*4] = w;
        }
        __syncthreads();
        #pragma unroll
        for (int kk = 0; kk < 16; kk++) {
            float hf[4], wf[12];
            #pragma unroll
            for (int m = 0; m < 4; m++)  hf[m] = Hs[kk*33 + ty*4 + m];
            #pragma unroll
            for (int n = 0; n < 12; n++) wf[n] = Ws2[kk*WN + n*32 + tx];
            #pragma unroll
            for (int m = 0; m < 4; m++)
                #pragma unroll
                for (int n = 0; n < 12; n++) acc[m][n] += hf[m]*wf[n];
        }
        __syncthreads();
    }

    // stash ew tile in smem (reuse)
    float* sEw = smem;
    #pragma unroll
    for (int m = 0; m < 4; m++)
        #pragma unroll
        for (int n = 0; n < 12; n++)
            sEw[(ty*4 + m)*WN + n*32 + tx] = acc[m][n];
    __syncthreads();

    // phase 2: 8 threads per row
    int r = tid >> 3;          // 0..31
    int l = tid & 7;           // 0..7
    int grow = row0 + r;
    int b = grow / EE;
    int e = grow - b*EE;
    int src = eidx[e];
    int dst = eidx[EE + e];
    const float* sh = &esh[grow*4];
    float sh0 = sh[0];
    const float* xg = &g_xnew[(b*NN + src)*CIN];
    float xr[CIN];
    #pragma unroll
    for (int i = 0; i < CIN; i++) xr[i] = __ldg(&xg[i]);

    const float* ewr = &sEw[r*WN];
    float o0a = 0.f, o0b = 0.f, d1 = 0.f;
    #pragma unroll
    for (int i = 0; i < CIN; i++) {
        float xi = xr[i];
        o0a += xi * ewr[i*16 + l];
        o0b += xi * ewr[i*16 + l + 8];
        d1  += xi * ewr[256 + i*8 + l];
    }
    float* aggp = &g_agg[(b*NN + dst)*OUTD];
    atomicAdd(&aggp[l],     ALPHA_C * sh0 * o0a);
    atomicAdd(&aggp[l + 8], ALPHA_C * sh0 * o0b);
    d1 *= ALPHA_C;
    atomicAdd(&aggp[16 + l*3 + 0], d1 * sh[1]);
    atomicAdd(&aggp[16 + l*3 + 1], d1 * sh[2]);
    atomicAdd(&aggp[16 + l*3 + 2], d1 * sh[3]);
}

// ---------------- mean-by-count + BN stats ----------------------------------
__global__ void stats_kernel() {
    int row = blockIdx.x * blockDim.x + threadIdx.x;
    float v[OUTD];
    if (row < BB*NN) {
        int n = row % NN;
        float inv = 1.0f / fmaxf(g_cnt[n], 1.0f);
        float4* p = (float4*)&g_agg[row*OUTD];
        #pragma unroll
        for (int t = 0; t < 10; t++) {
            float4 a = p[t];
            a.x *= inv; a.y *= inv; a.z *= inv; a.w *= inv;
            p[t] = a;
            v[t*4+0] = a.x; v[t*4+1] = a.y; v[t*4+2] = a.z; v[t*4+3] = a.w;
        }
    } else {
        #pragma unroll
        for (int c = 0; c < OUTD; c++) v[c] = 0.f;
    }
    #pragma unroll
    for (int c = 0; c < OUTD; c++) {
        float s = v[c], q = v[c]*v[c];
        #pragma unroll
        for (int off = 16; off > 0; off >>= 1) {
            s += __shfl_down_sync(0xffffffffu, s, off);
            q += __shfl_down_sync(0xffffffffu, q, off);
        }
        if ((threadIdx.x & 31) == 0) {
            atomicAdd(&g_sum[c],   s);
            atomicAdd(&g_sumsq[c], q);
        }
    }
}

// ---------------- batchnorm normalize ---------------------------------------
__global__ void norm_kernel(float* __restrict__ out,
                            const float* __restrict__ gamma,
                            const float* __restrict__ beta) {
    int i = blockIdx.x * blockDim.x + threadIdx.x;
    if (i >= BB*NN*OUTD) return;
    int c = i % OUTD;
    const float invM = 1.0f / M_TOT;
    float mu  = g_sum[c] * invM;
    float var = g_sumsq[c] * invM - mu*mu;
    out[i] = (g_agg[i] - mu) * rsqrtf(var + BN_EPS_C) * gamma[c] + beta[c];
}

// ---------------- launch ----------------------------------------------------
extern "C" void kernel_launch(void* const* d_in, const int* in_sizes, int n_in,
                              void* d_out, int out_size) {
    const float* x     = (const float*)d_in[0];
    const int*   eidx  = (const int*)  d_in[1];
    const float* ea    = (const float*)d_in[2];
    const float* esh   = (const float*)d_in[3];
    const float* wr    = (const float*)d_in[4];
    const float* wi    = (const float*)d_in[5];
    const float* w1    = (const float*)d_in[6];
    const float* b1    = (const float*)d_in[7];
    const float* w2    = (const float*)d_in[8];
    const float* b2    = (const float*)d_in[9];
    const float* gamma = (const float*)d_in[10];
    const float* beta  = (const float*)d_in[11];
    float* out = (float*)d_out;

    zero_kernel <<<(BB*NN*OUTD + 255)/256, 256>>>();
    xnew_kernel <<<(NN*CIN + 255)/256, 256>>>(x, wr, wi);
    count_kernel<<<(EE + 255)/256, 256>>>(eidx);
    gemm1_kernel<<<MROWS/64, 256>>>(ea, w1, b1);
    gemm2_msg_kernel<<<MROWS/32, 256>>>(w2, b2, eidx, esh);
    stats_kernel<<<(BB*NN + 255)/256, 256>>>();
    norm_kernel <<<(BB*NN*OUTD + 255)/256, 256>>>(out, gamma, beta);
}

// round 6
// speedup vs baseline: 2.0223x; 2.0223x over previous
#include <cuda_runtime.h>
#include <cuda_bf16.h>
#include <math.h>

#define BB   4
#define NN   10000
#define EE   100000
#define CIN  16
#define NF   128
#define WN   384
#define OUTD 40
#define MROWS (BB*EE)            // 400000
#define ALPHA_C 0.25f
#define BN_EPS_C 1e-5f
#define M_TOT 40000.0f           // B*N rows in BN stats
#define KPAD 136                 // bf16 smem row stride (272B = 17*16B, ldmatrix conflict-free)
#define EWPAD 132                // f32 smem row stride for ew tile
#define SMEM_BYTES (2*128*KPAD*2 + 2*128*KPAD*2)   // 69632 + 69632 = 139264

// ---------------- scratch (device globals; no allocations allowed) ----------
__device__ float g_xnew[BB*NN*CIN];
__device__ float g_agg[BB*NN*OUTD];
__device__ float g_cnt[NN];
__device__ float g_sum[OUTD];
__device__ float g_sumsq[OUTD];
__device__ __align__(16) __nv_bfloat16 g_w1t_hi[NF*NF];   // [n][k] transposed
__device__ __align__(16) __nv_bfloat16 g_w1t_lo[NF*NF];
__device__ __align__(16) __nv_bfloat16 g_w2t_hi[WN*NF];
__device__ __align__(16) __nv_bfloat16 g_w2t_lo[WN*NF];

// ---------------- zero scratch ----------------------------------------------
__global__ void zero_kernel() {
    int i = blockIdx.x * blockDim.x + threadIdx.x;
    if (i < BB*NN*OUTD) g_agg[i] = 0.0f;
    if (i < NN)         g_cnt[i] = 0.0f;
    if (i < OUTD) { g_sum[i] = 0.0f; g_sumsq[i] = 0.0f; }
}

// ---------------- weight transpose + bf16 hi/lo split ------------------------
__global__ void prep_kernel(const float* __restrict__ w1,
                            const float* __restrict__ w2) {
    int idx = blockIdx.x * blockDim.x + threadIdx.x;
    if (idx < NF*NF) {
        int n = idx / NF, k = idx % NF;
        float v = w1[k*NF + n];
        __nv_bfloat16 hi = __float2bfloat16(v);
        g_w1t_hi[idx] = hi;
        g_w1t_lo[idx] = __float2bfloat16(v - __bfloat162float(hi));
    }
    if (idx < WN*NF) {
        int n = idx / NF, k = idx % NF;
        float v = w2[k*WN + n];
        __nv_bfloat16 hi = __float2bfloat16(v);
        g_w2t_hi[idx] = hi;
        g_w2t_lo[idx] = __float2bfloat16(v - __bfloat162float(hi));
    }
}

// ---------------- closed-form FFT time mixing -------------------------------
__global__ void xnew_kernel(const float* __restrict__ x,
                            const float* __restrict__ wr,
                            const float* __restrict__ wi) {
    __shared__ float sWr[CIN][CIN];
    __shared__ float sWi[CIN][CIN];
    int t = threadIdx.x;
    {
        int i = t >> 4, o = t & 15;
        sWr[i][o] = wr[i*32 + o*2 + 0] + wr[i*32 + o*2 + 1];
        sWi[i][o] = wi[i*32 + o*2 + 0] + wi[i*32 + o*2 + 1];
    }
    __syncthreads();
    int idx = blockIdx.x * blockDim.x + t;
    if (idx >= NN*CIN) return;
    int n = idx >> 4, o = idx & 15;
    float x0r = 0.f, re1 = 0.f, im1 = 0.f;
    #pragma unroll
    for (int i = 0; i < CIN; i++) {
        float a0 = x[(0*NN + n)*CIN + i];
        float a1 = x[(1*NN + n)*CIN + i];
        float a2 = x[(2*NN + n)*CIN + i];
        float a3 = x[(3*NN + n)*CIN + i];
        float S = a0 + a1 + a2 + a3;
        float P = a0 - a2;
        float Q = a3 - a1;
        float wrv = sWr[i][o], wiv = sWi[i][o];
        x0r += S * wrv;
        re1 += P * wrv - Q * wiv;
        im1 += P * wiv + Q * wrv;
    }
    g_xnew[(0*NN + n)*CIN + o] = 0.25f*(x0r + 2.f*re1);
    g_xnew[(1*NN + n)*CIN + o] = 0.25f*(x0r - 2.f*im1);
    g_xnew[(2*NN + n)*CIN + o] = 0.25f*(x0r - 2.f*re1);
    g_xnew[(3*NN + n)*CIN + o] = 0.25f*(x0r + 2.f*im1);
}

// ---------------- per-node in-degree ----------------------------------------
__global__ void count_kernel(const int* __restrict__ eidx) {
    int e = blockIdx.x * blockDim.x + threadIdx.x;
    if (e < EE) atomicAdd(&g_cnt[eidx[EE + e]], 1.0f);
}

// ---------------- tensor-core helpers ---------------------------------------
__device__ __forceinline__ void mma_bf16(float* c, const unsigned* a, const unsigned* b) {
    asm volatile(
        "mma.sync.aligned.m16n8k16.row.col.f32.bf16.bf16.f32 "
        "{%0,%1,%2,%3}, {%4,%5,%6,%7}, {%8,%9}, {%0,%1,%2,%3};\n"
        : "+f"(c[0]), "+f"(c[1]), "+f"(c[2]), "+f"(c[3])
        : "r"(a[0]), "r"(a[1]), "r"(a[2]), "r"(a[3]), "r"(b[0]), "r"(b[1]));
}
__device__ __forceinline__ void ldmat4(unsigned* a, const __nv_bfloat16* p) {
    unsigned addr = (unsigned)__cvta_generic_to_shared(p);
    asm volatile("ldmatrix.sync.aligned.m8n8.x4.shared.b16 {%0,%1,%2,%3}, [%4];"
                 : "=r"(a[0]), "=r"(a[1]), "=r"(a[2]), "=r"(a[3]) : "r"(addr));
}

// 3-term split GEMM: acc += Ahi@Whi + Ahi@Wlo + Alo@Whi  (K=128 each)
// A: [m=128][k] row-major smem (stride KPAD); W: [n][k] smem (stride KPAD).
// Warp computes 128 rows x 16 cols (cols warp*16..+15). acc[mt][nt][4].
__device__ __forceinline__ void gemm_3term(
    const __nv_bfloat16* __restrict__ sAhi, const __nv_bfloat16* __restrict__ sAlo,
    const __nv_bfloat16* __restrict__ sWhi, const __nv_bfloat16* __restrict__ sWlo,
    int warp, int lane, float acc[8][2][4])
{
    #pragma unroll
    for (int term = 0; term < 3; term++) {
        const __nv_bfloat16* A = (term < 2) ? sAhi : sAlo;
        const __nv_bfloat16* W = (term == 1) ? sWlo : sWhi;
        // ldmatrix lane address: lanes 0-15 -> rows 0-15 @k0; lanes 16-31 -> rows 0-15 @k0+8
        const __nv_bfloat16* Arow = A + (lane & 15)*KPAD + (lane >> 4)*8;
        // B frag: n = lane/4 within n8 tile; k pair at (lane%4)*2 (+8)
        const __nv_bfloat16* Wb = W + (warp*16 + (lane >> 2))*KPAD + (lane & 3)*2;
        #pragma unroll
        for (int k0 = 0; k0 < 128; k0 += 16) {
            unsigned b0[2], b1[2];
            b0[0] = *(const unsigned*)&Wb[k0];
            b0[1] = *(const unsigned*)&Wb[k0 + 8];
            b1[0] = *(const unsigned*)&Wb[8*KPAD + k0];
            b1[1] = *(const unsigned*)&Wb[8*KPAD + k0 + 8];
            #pragma unroll
            for (int mt = 0; mt < 8; mt++) {
                unsigned a[4];
                ldmat4(a, Arow + mt*16*KPAD + k0);
                mma_bf16(acc[mt][0], a, b0);
                mma_bf16(acc[mt][1], a, b1);
            }
        }
    }
}

// ---------------- fused: GEMM1 + relu + GEMM2 + message + scatter -----------
__global__ __launch_bounds__(256, 1)
void fused_kernel(const float* __restrict__ ea,  const float* __restrict__ b1g,
                  const float* __restrict__ b2g, const int* __restrict__ eidx,
                  const float* __restrict__ esh)
{
    extern __shared__ char smem_raw[];
    __nv_bfloat16* sAhi = (__nv_bfloat16*)smem_raw;            // 128 x KPAD
    __nv_bfloat16* sAlo = sAhi + 128*KPAD;
    char* region = smem_raw + (size_t)2*128*KPAD*2;            // union region
    __nv_bfloat16* sWhi = (__nv_bfloat16*)region;              // 128 x KPAD
    __nv_bfloat16* sWlo = sWhi + 128*KPAD;
    float* sEw = (float*)region;                               // 128 x EWPAD

    const int tid  = threadIdx.x;
    const int warp = tid >> 5, lane = tid & 31;
    const int row0 = blockIdx.x * 128;

    // ---- load A tile (128x128 f32) and split into bf16 hi/lo ----
    for (int idx = tid; idx < 128*32; idx += 256) {
        int r = idx >> 5, q = (idx & 31) << 2;
        float4 v = *(const float4*)&ea[(size_t)(row0 + r)*NF + q];
        __nv_bfloat16 hx = __float2bfloat16(v.x);
        __nv_bfloat16 hy = __float2bfloat16(v.y);
        __nv_bfloat16 hz = __float2bfloat16(v.z);
        __nv_bfloat16 hw = __float2bfloat16(v.w);
        __nv_bfloat162* ph = (__nv_bfloat162*)&sAhi[r*KPAD + q];
        ph[0] = __nv_bfloat162(hx, hy);
        ph[1] = __nv_bfloat162(hz, hw);
        __nv_bfloat162* pl = (__nv_bfloat162*)&sAlo[r*KPAD + q];
        pl[0] = __nv_bfloat162(__float2bfloat16(v.x - __bfloat162float(hx)),
                               __float2bfloat16(v.y - __bfloat162float(hy)));
        pl[1] = __nv_bfloat162(__float2bfloat16(v.z - __bfloat162float(hz)),
                               __float2bfloat16(v.w - __bfloat162float(hw)));
    }
    // ---- stage W1T hi/lo ----
    for (int idx = tid; idx < 128*16; idx += 256) {
        int n = idx >> 4, q = (idx & 15) << 3;
        *(float4*)&sWhi[n*KPAD + q] = *(const float4*)&g_w1t_hi[n*NF + q];
        *(float4*)&sWlo[n*KPAD + q] = *(const float4*)&g_w1t_lo[n*NF + q];
    }
    __syncthreads();

    // ---- GEMM1: H = relu(A@W1 + b1) ----
    float acc[8][2][4];
    {
        int colb = warp*16 + (lane & 3)*2;
        #pragma unroll
        for (int nt = 0; nt < 2; nt++) {
            float bc0 = b1g[colb + nt*8], bc1 = b1g[colb + nt*8 + 1];
            #pragma unroll
            for (int mt = 0; mt < 8; mt++) {
                acc[mt][nt][0] = bc0; acc[mt][nt][1] = bc1;
                acc[mt][nt][2] = bc0; acc[mt][nt][3] = bc1;
            }
        }
    }
    gemm_3term(sAhi, sAlo, sWhi, sWlo, warp, lane, acc);
    __syncthreads();   // everyone done reading sA

    // ---- relu + re-split H into sAhi/sAlo ----
    {
        int c0 = warp*16 + (lane & 3)*2;
        int r0 = lane >> 2;
        #pragma unroll
        for (int mt = 0; mt < 8; mt++) {
            #pragma unroll
            for (int nt = 0; nt < 2; nt++) {
                int col = c0 + nt*8;
                #pragma unroll
                for (int half = 0; half < 2; half++) {
                    int row = mt*16 + r0 + half*8;
                    float h0 = fmaxf(acc[mt][nt][half*2 + 0], 0.f);
                    float h1 = fmaxf(acc[mt][nt][half*2 + 1], 0.f);
                    __nv_bfloat16 hi0 = __float2bfloat16(h0);
                    __nv_bfloat16 hi1 = __float2bfloat16(h1);
                    *(__nv_bfloat162*)&sAhi[row*KPAD + col] = __nv_bfloat162(hi0, hi1);
                    *(__nv_bfloat162*)&sAlo[row*KPAD + col] =
                        __nv_bfloat162(__float2bfloat16(h0 - __bfloat162float(hi0)),
                                       __float2bfloat16(h1 - __bfloat162float(hi1)));
                }
            }
        }
    }

    // ---- per-edge metadata (2 threads per row) ----
    const int r_e = tid >> 1, l = tid & 1;
    const int grow = row0 + r_e;
    const int b = grow / EE;
    const int e = grow - b*EE;
    const int src = eidx[e];
    const int dst = eidx[EE + e];
    const float4 sh = *(const float4*)&esh[(size_t)grow*4];
    float xg[CIN];
    {
        const float4* xgp = (const float4*)&g_xnew[((size_t)b*NN + src)*CIN];
        #pragma unroll
        for (int t4 = 0; t4 < 4; t4++) {
            float4 v = xgp[t4];
            xg[t4*4+0] = v.x; xg[t4*4+1] = v.y; xg[t4*4+2] = v.z; xg[t4*4+3] = v.w;
        }
    }
    float o0[8] = {0,0,0,0,0,0,0,0};
    float d1[4] = {0,0,0,0};

    // ---- GEMM2 in 3 N-chunks of 128, fused message contraction ----
    for (int ch = 0; ch < 3; ch++) {
        __syncthreads();   // previous sEw consumers done / H writes visible (ch==0)
        for (int idx = tid; idx < 128*16; idx += 256) {
            int n = idx >> 4, q = (idx & 15) << 3;
            *(float4*)&sWhi[n*KPAD + q] = *(const float4*)&g_w2t_hi[(size_t)(ch*128 + n)*NF + q];
            *(float4*)&sWlo[n*KPAD + q] = *(const float4*)&g_w2t_lo[(size_t)(ch*128 + n)*NF + q];
        }
        __syncthreads();

        {
            int colb = ch*128 + warp*16 + (lane & 3)*2;
            #pragma unroll
            for (int nt = 0; nt < 2; nt++) {
                float bc0 = b2g[colb + nt*8], bc1 = b2g[colb + nt*8 + 1];
                #pragma unroll
                for (int mt = 0; mt < 8; mt++) {
                    acc[mt][nt][0] = bc0; acc[mt][nt][1] = bc1;
                    acc[mt][nt][2] = bc0; acc[mt][nt][3] = bc1;
                }
            }
        }
        gemm_3term(sAhi, sAlo, sWhi, sWlo, warp, lane, acc);
        __syncthreads();   // done reading sW; region can become sEw

        {
            int c0 = warp*16 + (lane & 3)*2;
            int r0 = lane >> 2;
            #pragma unroll
            for (int mt = 0; mt < 8; mt++) {
                #pragma unroll
                for (int nt = 0; nt < 2; nt++) {
                    int col = c0 + nt*8;
                    *(float2*)&sEw[(mt*16 + r0    )*EWPAD + col] =
                        make_float2(acc[mt][nt][0], acc[mt][nt][1]);
                    *(float2*)&sEw[(mt*16 + r0 + 8)*EWPAD + col] =
                        make_float2(acc[mt][nt][2], acc[mt][nt][3]);
                }
            }
        }
        __syncthreads();

        // message partial accumulation from this ew chunk
        const float* er = &sEw[r_e*EWPAD];
        if (ch == 0) {
            #pragma unroll
            for (int oi = 0; oi < 8; oi++) {
                int c = l*8 + oi;
                #pragma unroll
                for (int i = 0; i < 8; i++) o0[oi] += xg[i] * er[i*16 + c];
            }
        } else if (ch == 1) {
            #pragma unroll
            for (int oi = 0; oi < 8; oi++) {
                int c = l*8 + oi;
                #pragma unroll
                for (int i = 0; i < 8; i++) o0[oi] += xg[i+8] * er[i*16 + c];
            }
        } else {
            #pragma unroll
            for (int oi = 0; oi < 4; oi++) {
                int c = l*4 + oi;
                #pragma unroll
                for (int i = 0; i < 16; i++) d1[oi] += xg[i] * er[i*8 + c];
            }
        }
    }

    // ---- scatter ----
    float* aggp = &g_agg[((size_t)b*NN + dst)*OUTD];
    float s0 = ALPHA_C * sh.x;
    #pragma unroll
    for (int oi = 0; oi < 8; oi++)
        atomicAdd(&aggp[l*8 + oi], s0 * o0[oi]);
    #pragma unroll
    for (int oi = 0; oi < 4; oi++) {
        int cch = l*4 + oi;
        float v = ALPHA_C * d1[oi];
        atomicAdd(&aggp[16 + cch*3 + 0], v * sh.y);
        atomicAdd(&aggp[16 + cch*3 + 1], v * sh.z);
        atomicAdd(&aggp[16 + cch*3 + 2], v * sh.w);
    }
}

// ---------------- mean-by-count + BN stats ----------------------------------
__global__ void stats_kernel() {
    int row = blockIdx.x * blockDim.x + threadIdx.x;
    float v[OUTD];
    if (row < BB*NN) {
        int n = row % NN;
        float inv = 1.0f / fmaxf(g_cnt[n], 1.0f);
        float4* p = (float4*)&g_agg[row*OUTD];
        #pragma unroll
        for (int t = 0; t < 10; t++) {
            float4 a = p[t];
            a.x *= inv; a.y *= inv; a.z *= inv; a.w *= inv;
            p[t] = a;
            v[t*4+0] = a.x; v[t*4+1] = a.y; v[t*4+2] = a.z; v[t*4+3] = a.w;
        }
    } else {
        #pragma unroll
        for (int c = 0; c < OUTD; c++) v[c] = 0.f;
    }
    #pragma unroll
    for (int c = 0; c < OUTD; c++) {
        float s = v[c], q = v[c]*v[c];
        #pragma unroll
        for (int off = 16; off > 0; off >>= 1) {
            s += __shfl_down_sync(0xffffffffu, s, off);
            q += __shfl_down_sync(0xffffffffu, q, off);
        }
        if ((threadIdx.x & 31) == 0) {
            atomicAdd(&g_sum[c],   s);
            atomicAdd(&g_sumsq[c], q);
        }
    }
}

// ---------------- batchnorm normalize ---------------------------------------
__global__ void norm_kernel(float* __restrict__ out,
                            const float* __restrict__ gamma,
                            const float* __restrict__ beta) {
    int i = blockIdx.x * blockDim.x + threadIdx.x;
    if (i >= BB*NN*OUTD) return;
    int c = i % OUTD;
    const float invM = 1.0f / M_TOT;
    float mu  = g_sum[c] * invM;
    float var = g_sumsq[c] * invM - mu*mu;
    out[i] = (g_agg[i] - mu) * rsqrtf(var + BN_EPS_C) * gamma[c] + beta[c];
}

// ---------------- launch ----------------------------------------------------
extern "C" void kernel_launch(void* const* d_in, const int* in_sizes, int n_in,
                              void* d_out, int out_size) {
    const float* x     = (const float*)d_in[0];
    const int*   eidx  = (const int*)  d_in[1];
    const float* ea    = (const float*)d_in[2];
    const float* esh   = (const float*)d_in[3];
    const float* wr    = (const float*)d_in[4];
    const float* wi    = (const float*)d_in[5];
    const float* w1    = (const float*)d_in[6];
    const float* b1    = (const float*)d_in[7];
    const float* w2    = (const float*)d_in[8];
    const float* b2    = (const float*)d_in[9];
    const float* gamma = (const float*)d_in[10];
    const float* beta  = (const float*)d_in[11];
    float* out = (float*)d_out;

    cudaFuncSetAttribute(fused_kernel,
                         cudaFuncAttributeMaxDynamicSharedMemorySize, SMEM_BYTES);

    zero_kernel <<<(BB*NN*OUTD + 255)/256, 256>>>();
    xnew_kernel <<<(NN*CIN + 255)/256, 256>>>(x, wr, wi);
    count_kernel<<<(EE + 255)/256, 256>>>(eidx);
    prep_kernel <<<(WN*NF + 255)/256, 256>>>(w1, w2);
    fused_kernel<<<MROWS/128, 256, SMEM_BYTES>>>(ea, b1, b2, eidx, esh);
    stats_kernel<<<(BB*NN + 255)/256, 256>>>();
    norm_kernel <<<(BB*NN*OUTD + 255)/256, 256>>>(out, gamma, beta);
}